// round 1
// baseline (speedup 1.0000x reference)
#include <cuda_runtime.h>

#define D_DIM 256
#define N_MAX 4096
#define M_MAX 16384
#define EPSV 1e-12f

// Scratch (no allocations allowed in kernel_launch).
__device__ float g_x2[N_MAX];      // ||x_i||^2
__device__ float g_y2[M_MAX];      // ||y_j||^2
__device__ float g_rowsum[N_MAX];  // sum_j dist(i,j)

// ---------------------------------------------------------------------------
// Zero scratch + output (graph replays re-run this every iteration).
// ---------------------------------------------------------------------------
__global__ void zero_kernel(float* out, int N) {
    int t = blockIdx.x * blockDim.x + threadIdx.x;
    if (t < N) g_rowsum[t] = 0.0f;
    if (t == 0) out[0] = 0.0f;
}

// ---------------------------------------------------------------------------
// Squared norms: one warp per row (256 floats = 64 float4; 2 float4 per lane).
// Rows [0,N) -> g_x2 from X, rows [N, N+M) -> g_y2 from Y.
// ---------------------------------------------------------------------------
__global__ void norms_kernel(const float* __restrict__ X,
                             const float* __restrict__ Y,
                             int N, int M) {
    int warp = (blockIdx.x * blockDim.x + threadIdx.x) >> 5;
    int lane = threadIdx.x & 31;
    int R = N + M;
    if (warp >= R) return;

    const float4* p;
    int row;
    if (warp < N) { p = (const float4*)X; row = warp; }
    else          { p = (const float4*)Y; row = warp - N; }

    float4 v1 = p[row * 64 + lane];
    float4 v2 = p[row * 64 + 32 + lane];
    float s = v1.x * v1.x + v1.y * v1.y + v1.z * v1.z + v1.w * v1.w
            + v2.x * v2.x + v2.y * v2.y + v2.z * v2.z + v2.w * v2.w;
#pragma unroll
    for (int o = 16; o; o >>= 1) s += __shfl_xor_sync(0xffffffffu, s, o);
    if (lane == 0) {
        if (warp < N) g_x2[row] = s;
        else          g_y2[row] = s;
    }
}

// ---------------------------------------------------------------------------
// Fused distance GEMM + row-sum.
// Block computes a 128(i) x 128(j) tile of XY^T, K=256 in chunks of 8.
// 256 threads, each owns an 8x8 register micro-tile with split mapping
// (4 consecutive + 4 at +64) for conflict-free LDS.128.
// Epilogue: dist = sqrt(max(x2+y2-2xy,0)+eps) via v*rsqrt(v); reduce per-row
// into shared, then one global atomicAdd per row per block.
// ---------------------------------------------------------------------------
__global__ __launch_bounds__(256, 2)
void dist_kernel(const float* __restrict__ X,
                 const float* __restrict__ Y,
                 int N, int M) {
    __shared__ float As[8][136];
    __shared__ float Bs[8][136];
    __shared__ float red[128];

    const int tid   = threadIdx.x;
    const int iBase = blockIdx.y * 128;
    const int jBase = blockIdx.x * 128;
    const int tx = tid & 15;   // 16 col-groups
    const int ty = tid >> 4;   // 16 row-groups

    float acc[8][8];
#pragma unroll
    for (int r = 0; r < 8; r++)
#pragma unroll
        for (int c = 0; c < 8; c++) acc[r][c] = 0.0f;

    // Loader mapping: each thread loads one float4 of A and one of B per k-tile.
    const int lrow = tid >> 1;          // 0..127
    const int lk   = (tid & 1) * 4;     // 0 or 4
    const float* Aptr = X + (long long)(iBase + lrow) * D_DIM + lk;
    const float* Bptr = Y + (long long)(jBase + lrow) * D_DIM + lk;

    for (int k0 = 0; k0 < D_DIM; k0 += 8) {
        float4 av = *(const float4*)(Aptr + k0);
        float4 bv = *(const float4*)(Bptr + k0);
        __syncthreads();   // previous tile's reads done before overwrite
        As[lk + 0][lrow] = av.x; As[lk + 1][lrow] = av.y;
        As[lk + 2][lrow] = av.z; As[lk + 3][lrow] = av.w;
        Bs[lk + 0][lrow] = bv.x; Bs[lk + 1][lrow] = bv.y;
        Bs[lk + 2][lrow] = bv.z; Bs[lk + 3][lrow] = bv.w;
        __syncthreads();

#pragma unroll
        for (int kk = 0; kk < 8; kk++) {
            float a[8], b[8];
            // rows: ty*4 + 0..3 and 64 + ty*4 + 0..3
#pragma unroll
            for (int r = 0; r < 4; r++) {
                a[r]     = As[kk][ty * 4 + r];
                a[r + 4] = As[kk][64 + ty * 4 + r];
            }
#pragma unroll
            for (int c = 0; c < 4; c++) {
                b[c]     = Bs[kk][tx * 4 + c];
                b[c + 4] = Bs[kk][64 + tx * 4 + c];
            }
#pragma unroll
            for (int r = 0; r < 8; r++)
#pragma unroll
                for (int c = 0; c < 8; c++)
                    acc[r][c] += a[r] * b[c];
        }
    }

    // Epilogue
    float x2v[8], y2v[8];
#pragma unroll
    for (int r = 0; r < 8; r++) {
        int ri = ty * 4 + (r & 3) + ((r >> 2) * 64);
        x2v[r] = g_x2[iBase + ri];
    }
#pragma unroll
    for (int c = 0; c < 8; c++) {
        int cj = tx * 4 + (c & 3) + ((c >> 2) * 64);
        y2v[c] = g_y2[jBase + cj];
    }

    if (tid < 128) red[tid] = 0.0f;
    __syncthreads();

#pragma unroll
    for (int r = 0; r < 8; r++) {
        int ri = ty * 4 + (r & 3) + ((r >> 2) * 64);
        float rs = 0.0f;
#pragma unroll
        for (int c = 0; c < 8; c++) {
            float d2 = fmaxf(x2v[r] + y2v[c] - 2.0f * acc[r][c], 0.0f) + EPSV;
            rs += d2 * rsqrtf(d2);   // = sqrt(d2)
        }
        atomicAdd(&red[ri], rs);
    }
    __syncthreads();
    if (tid < 128) atomicAdd(&g_rowsum[iBase + tid], red[tid]);
}

// ---------------------------------------------------------------------------
// loss = sum_{i,j} sqrt((d_i - d_j)^2 + eps),  d_i = rowsum_i / M.
// One block per i; all d cached in shared.
// ---------------------------------------------------------------------------
__global__ void loss_kernel(float* __restrict__ out, int N, float invM) {
    __shared__ float sd[N_MAX];
    __shared__ float wsum[8];
    const int tid = threadIdx.x;

    for (int t = tid; t < N; t += blockDim.x)
        sd[t] = g_rowsum[t] * invM;
    __syncthreads();

    const float di = sd[blockIdx.x];
    float local = 0.0f;
    for (int j = tid; j < N; j += blockDim.x) {
        float df = di - sd[j];
        float v = df * df + EPSV;
        local += v * rsqrtf(v);     // = sqrt(v)
    }
#pragma unroll
    for (int o = 16; o; o >>= 1) local += __shfl_xor_sync(0xffffffffu, local, o);
    int lane = tid & 31, warp = tid >> 5;
    if (lane == 0) wsum[warp] = local;
    __syncthreads();
    if (tid == 0) {
        float s = 0.0f;
#pragma unroll
        for (int w = 0; w < 8; w++) s += wsum[w];
        atomicAdd(out, s);
    }
}

// ---------------------------------------------------------------------------
extern "C" void kernel_launch(void* const* d_in, const int* in_sizes, int n_in,
                              void* d_out, int out_size) {
    const float* X = (const float*)d_in[0];  // ide_feats [N, 256]
    const float* Y = (const float*)d_in[1];  // u_feats   [M, 256]
    float* out = (float*)d_out;

    const int N = in_sizes[0] / D_DIM;   // 4096
    const int M = in_sizes[1] / D_DIM;   // 16384

    zero_kernel<<<(N + 255) / 256, 256>>>(out, N);

    const int R = N + M;
    norms_kernel<<<(R * 32 + 255) / 256, 256>>>(X, Y, N, M);

    dim3 grid(M / 128, N / 128);
    dist_kernel<<<grid, 256>>>(X, Y, N, M);

    loss_kernel<<<N, 256>>>(out, N, 1.0f / (float)M);
}

// round 3
// speedup vs baseline: 6.3021x; 6.3021x over previous
#include <cuda_runtime.h>
#include <cstdint>

#define D_DIM 256
#define N_MAX 4096
#define M_MAX 16384
#define EPSV 1e-12f

// ---------------------------------------------------------------------------
// Scratch (static device arrays; no allocations allowed).
// ---------------------------------------------------------------------------
__device__ float g_x2[N_MAX];
__device__ float g_y2[M_MAX];
__device__ float g_rowsum[N_MAX];
__device__ __align__(16) uint32_t g_Xh[N_MAX * (D_DIM / 2)];   // bf16x2 packed
__device__ __align__(16) uint32_t g_Yh[M_MAX * (D_DIM / 2)];   // bf16x2 packed

// ---------------------------------------------------------------------------
// PTX helpers (arch-portable: ldmatrix / mma.sync / cp.async only)
// ---------------------------------------------------------------------------
__device__ __forceinline__ uint32_t smem_u32(const void* p) {
    uint32_t a;
    asm("{ .reg .u64 t; cvta.to.shared.u64 t, %1; cvt.u32.u64 %0, t; }" : "=r"(a) : "l"(p));
    return a;
}
#define CP_ASYNC16(dst, src) asm volatile("cp.async.cg.shared.global [%0], [%1], 16;" :: "r"(dst), "l"(src) : "memory")
#define CP_COMMIT()          asm volatile("cp.async.commit_group;" ::: "memory")
#define CP_WAIT0()           asm volatile("cp.async.wait_group 0;" ::: "memory")

__device__ __forceinline__ void ldmatrix_x4(uint32_t* r, uint32_t addr) {
    asm volatile("ldmatrix.sync.aligned.m8n8.x4.shared.b16 {%0,%1,%2,%3}, [%4];"
                 : "=r"(r[0]), "=r"(r[1]), "=r"(r[2]), "=r"(r[3]) : "r"(addr));
}
__device__ __forceinline__ void ldmatrix_x2(uint32_t* r, uint32_t addr) {
    asm volatile("ldmatrix.sync.aligned.m8n8.x2.shared.b16 {%0,%1}, [%2];"
                 : "=r"(r[0]), "=r"(r[1]) : "r"(addr));
}
__device__ __forceinline__ void mma_bf16(float* c, const uint32_t* a, const uint32_t* b) {
    asm volatile("mma.sync.aligned.m16n8k16.row.col.f32.bf16.bf16.f32 "
                 "{%0,%1,%2,%3}, {%4,%5,%6,%7}, {%8,%9}, {%0,%1,%2,%3};"
                 : "+f"(c[0]), "+f"(c[1]), "+f"(c[2]), "+f"(c[3])
                 : "r"(a[0]), "r"(a[1]), "r"(a[2]), "r"(a[3]), "r"(b[0]), "r"(b[1]));
}

// ---------------------------------------------------------------------------
// zero scratch + output
// ---------------------------------------------------------------------------
__global__ void zero_kernel(float* out, int N) {
    int t = blockIdx.x * blockDim.x + threadIdx.x;
    if (t < N) g_rowsum[t] = 0.0f;
    if (t == 0) out[0] = 0.0f;
}

// ---------------------------------------------------------------------------
// Fused prep: one pass over fp32 inputs -> bf16 pack + squared norms.
// One warp per row.
// ---------------------------------------------------------------------------
__global__ void prep_kernel(const float* __restrict__ X,
                            const float* __restrict__ Y, int N, int M) {
    int warp = (blockIdx.x * blockDim.x + threadIdx.x) >> 5;
    int lane = threadIdx.x & 31;
    if (warp >= N + M) return;
    const float4* src; uint2* dst; float* nrm; int row;
    if (warp < N) { src = (const float4*)X; dst = (uint2*)g_Xh; nrm = g_x2; row = warp; }
    else          { src = (const float4*)Y; dst = (uint2*)g_Yh; nrm = g_y2; row = warp - N; }

    float4 v1 = src[row * 64 + lane];
    float4 v2 = src[row * 64 + 32 + lane];
    float s = v1.x*v1.x + v1.y*v1.y + v1.z*v1.z + v1.w*v1.w
            + v2.x*v2.x + v2.y*v2.y + v2.z*v2.z + v2.w*v2.w;
#pragma unroll
    for (int o = 16; o; o >>= 1) s += __shfl_xor_sync(0xffffffffu, s, o);
    if (lane == 0) nrm[row] = s;

    uint2 p1, p2;
    asm("cvt.rn.bf16x2.f32 %0, %1, %2;" : "=r"(p1.x) : "f"(v1.y), "f"(v1.x));
    asm("cvt.rn.bf16x2.f32 %0, %1, %2;" : "=r"(p1.y) : "f"(v1.w), "f"(v1.z));
    asm("cvt.rn.bf16x2.f32 %0, %1, %2;" : "=r"(p2.x) : "f"(v2.y), "f"(v2.x));
    asm("cvt.rn.bf16x2.f32 %0, %1, %2;" : "=r"(p2.y) : "f"(v2.w), "f"(v2.z));
    dst[row * 64 + lane]      = p1;
    dst[row * 64 + 32 + lane] = p2;
}

// ---------------------------------------------------------------------------
// Fused distance GEMM via mma.sync bf16.
// CTA = 128(i) x 128(j), K=256 in 4 chunks of 64, double-buffered cp.async.
// 8 warps, each 64(i) x 32(j): 4 i-frags(16) x 4 n-frags(8), m16n8k16.
// SMEM rows padded to 72 bf16 (144B) -> conflict-free ldmatrix.
// ---------------------------------------------------------------------------
#define ROWB   144           // padded row bytes (72 bf16)
#define TILE_B (128 * ROWB)  // 18432 per tile buffer
#define OFF_A  0
#define OFF_B  (2 * TILE_B)
#define OFF_X2 (4 * TILE_B)
#define OFF_Y2 (4 * TILE_B + 512)
#define OFF_RED (4 * TILE_B + 1024)
#define SMEM_DYN (4 * TILE_B + 1536)

__global__ __launch_bounds__(256, 2)
void dist_kernel(int N, int M) {
    extern __shared__ __align__(16) char smem[];
    const uint32_t sbase = smem_u32(smem);
    float* x2s = (float*)(smem + OFF_X2);
    float* y2s = (float*)(smem + OFF_Y2);
    float* red = (float*)(smem + OFF_RED);

    const int tid  = threadIdx.x;
    const int wid  = tid >> 5;
    const int lane = tid & 31;
    const int iBase = blockIdx.y * 128;
    const int jBase = blockIdx.x * 128;
    const int iw = (wid >> 2) * 64;
    const int jw = (wid & 3) * 32;

    const uint4* Ag = (const uint4*)g_Xh + (size_t)iBase * 32;
    const uint4* Bg = (const uint4*)g_Yh + (size_t)jBase * 32;

    // row/quad this thread loads (4 chunks of A, 4 of B per k-tile)
    const int lrow = tid >> 1;                 // base row pattern

    float acc[4][4][4];
#pragma unroll
    for (int a = 0; a < 4; a++)
#pragma unroll
        for (int b = 0; b < 4; b++)
#pragma unroll
            for (int c = 0; c < 4; c++) acc[a][b][c] = 0.0f;

    // norms into smem
    if (tid < 128) x2s[tid] = g_x2[iBase + tid];
    else           y2s[tid - 128] = g_y2[jBase + tid - 128];
    if (tid < 128) red[tid] = 0.0f;

    // tile loader: idx in [0,1024): row = idx>>3, quad = idx&7
    auto load_tiles = [&](int buf, int kq) {
#pragma unroll
        for (int t = 0; t < 4; t++) {
            int idx = tid + t * 256;
            int row = idx >> 3, q = idx & 7;
            CP_ASYNC16(sbase + OFF_A + buf * TILE_B + row * ROWB + q * 16,
                       (const void*)(Ag + row * 32 + kq + q));
        }
#pragma unroll
        for (int t = 0; t < 4; t++) {
            int idx = tid + t * 256;
            int row = idx >> 3, q = idx & 7;
            CP_ASYNC16(sbase + OFF_B + buf * TILE_B + row * ROWB + q * 16,
                       (const void*)(Bg + row * 32 + kq + q));
        }
        CP_COMMIT();
    };

    load_tiles(0, 0);
    CP_WAIT0();
    __syncthreads();

    const int l15 = lane & 15;
#pragma unroll
    for (int kt = 0; kt < 4; kt++) {
        const int buf = kt & 1;
        if (kt < 3) load_tiles(buf ^ 1, (kt + 1) * 8);

        const uint32_t sA = sbase + OFF_A + buf * TILE_B;
        const uint32_t sB = sbase + OFF_B + buf * TILE_B;
#pragma unroll
        for (int ks = 0; ks < 4; ks++) {
            uint32_t afr[4][4], bfr[4][2];
#pragma unroll
            for (int mf = 0; mf < 4; mf++)
                ldmatrix_x4(afr[mf], sA + (iw + mf * 16 + l15) * ROWB
                                        + ks * 32 + (lane >> 4) * 16);
#pragma unroll
            for (int nf = 0; nf < 4; nf++)
                ldmatrix_x2(bfr[nf], sB + (jw + nf * 8 + (l15 & 7)) * ROWB
                                        + ks * 32 + (l15 >> 3) * 16);
#pragma unroll
            for (int mf = 0; mf < 4; mf++)
#pragma unroll
                for (int nf = 0; nf < 4; nf++)
                    mma_bf16(acc[mf][nf], afr[mf], bfr[nf]);
        }
        if (kt < 3) { CP_WAIT0(); __syncthreads(); }
    }
    __syncthreads();   // red[] zeroed + x2s/y2s visible; tiles no longer needed

    // Epilogue: dist + per-row reduction.
#pragma unroll
    for (int mf = 0; mf < 4; mf++) {
        const int r0 = iw + mf * 16 + (lane >> 2);
        const float x20 = x2s[r0], x21 = x2s[r0 + 8];
        float rs0 = 0.0f, rs1 = 0.0f;
#pragma unroll
        for (int nf = 0; nf < 4; nf++) {
            const int j0 = jw + nf * 8 + (lane & 3) * 2;
            const float y20 = y2s[j0], y21 = y2s[j0 + 1];
            const float* c = acc[mf][nf];
            float d2;
            d2 = fmaxf(fmaf(-2.0f, c[0], x20 + y20), 0.0f) + EPSV; rs0 += d2 * rsqrtf(d2);
            d2 = fmaxf(fmaf(-2.0f, c[1], x20 + y21), 0.0f) + EPSV; rs0 += d2 * rsqrtf(d2);
            d2 = fmaxf(fmaf(-2.0f, c[2], x21 + y20), 0.0f) + EPSV; rs1 += d2 * rsqrtf(d2);
            d2 = fmaxf(fmaf(-2.0f, c[3], x21 + y21), 0.0f) + EPSV; rs1 += d2 * rsqrtf(d2);
        }
        rs0 += __shfl_xor_sync(0xffffffffu, rs0, 1);
        rs0 += __shfl_xor_sync(0xffffffffu, rs0, 2);
        rs1 += __shfl_xor_sync(0xffffffffu, rs1, 1);
        rs1 += __shfl_xor_sync(0xffffffffu, rs1, 2);
        if ((lane & 3) == 0) {
            atomicAdd(&red[r0], rs0);
            atomicAdd(&red[r0 + 8], rs1);
        }
    }
    __syncthreads();
    if (tid < 128) atomicAdd(&g_rowsum[iBase + tid], red[tid]);
}

// ---------------------------------------------------------------------------
// loss = sum_{i,j} sqrt((d_i - d_j)^2 + eps), d_i = rowsum_i / M.
// ---------------------------------------------------------------------------
__global__ void loss_kernel(float* __restrict__ out, int N, float invM) {
    __shared__ __align__(16) float sd[N_MAX];
    __shared__ float wsum[8];
    const int tid = threadIdx.x;
    for (int t = tid; t < N; t += blockDim.x) sd[t] = g_rowsum[t] * invM;
    __syncthreads();
    const float di = sd[blockIdx.x];
    float local = 0.0f;
    for (int j = tid * 4; j < N; j += blockDim.x * 4) {
        float4 v = *(const float4*)&sd[j];
        float df, s;
        df = di - v.x; s = df * df + EPSV; local += s * rsqrtf(s);
        df = di - v.y; s = df * df + EPSV; local += s * rsqrtf(s);
        df = di - v.z; s = df * df + EPSV; local += s * rsqrtf(s);
        df = di - v.w; s = df * df + EPSV; local += s * rsqrtf(s);
    }
#pragma unroll
    for (int o = 16; o; o >>= 1) local += __shfl_xor_sync(0xffffffffu, local, o);
    int lane = tid & 31, warp = tid >> 5;
    if (lane == 0) wsum[warp] = local;
    __syncthreads();
    if (tid == 0) {
        float s = 0.0f;
#pragma unroll
        for (int w = 0; w < 8; w++) s += wsum[w];
        atomicAdd(out, s);
    }
}

// ---------------------------------------------------------------------------
extern "C" void kernel_launch(void* const* d_in, const int* in_sizes, int n_in,
                              void* d_out, int out_size) {
    const float* X = (const float*)d_in[0];
    const float* Y = (const float*)d_in[1];
    float* out = (float*)d_out;
    const int N = in_sizes[0] / D_DIM;   // 4096
    const int M = in_sizes[1] / D_DIM;   // 16384

    static int attr_done = 0;
    if (!attr_done) {
        cudaFuncSetAttribute(dist_kernel,
                             cudaFuncAttributeMaxDynamicSharedMemorySize, SMEM_DYN);
        attr_done = 1;
    }

    zero_kernel<<<(N + 255) / 256, 256>>>(out, N);
    prep_kernel<<<((N + M) * 32 + 255) / 256, 256>>>(X, Y, N, M);
    dim3 grid(M / 128, N / 128);
    dist_kernel<<<grid, 256, SMEM_DYN>>>(N, M);
    loss_kernel<<<N, 256>>>(out, N, 1.0f / (float)M);
}